// round 17
// baseline (speedup 1.0000x reference)
#include <cuda_runtime.h>
#include <cuda_bf16.h>
#include <cstdint>

// DEQ via warp-level bf16 HMMA, c folded into the GEMM (K = 144, 9 k-tiles):
//   z~ = [z(128) | x_hi(4) | x_hi(4) | x_lo(4) | 1 | 1 | 0 0]
//   W~ = [B      | Aw_hi   | Aw_lo   | Aw_hi   | b_hi | b_lo | 0 0]
// 3 tanh applications; y = z3.h + hb fused into the last GEMM iteration.
// R17: 32-row bands per warp (two transient A-fragment sets) so each
// B-fragment load feeds 4 accumulator chains -> W smem traffic per row
// halved (L1 floor ~21us -> ~12us), LDSM/MMA halved, ILP doubled.
// 512 threads (16 warps, 4/SMSP, 128-reg cap), z in per-warp SMEM,
// per-CTA SMEM work counter, __syncwarp only, persistent grid.

#define THREADS 512
#define NWARPS  16
#define LDW     304        // bytes per W~/Z row (144 bf16 = 288 B + 16 pad)
#define ZSLICE  (32 * LDW) // 9728 B per warp (32-row band)
#define SM_W    0          // 128 * 304 = 38912 B
#define SM_Z    38912      // 16 * 9728 = 155648 B
#define SM_H    194560     // 512 B
#define SM_CNT  195072     // 4 B work counter
#define SM_TOTAL 195104

__device__ __forceinline__ float tanh_exact(float v) {
    float e = __expf(2.0f * v);
    return 1.0f - __fdividef(2.0f, e + 1.0f);
}
__device__ __forceinline__ float tanh_apx(float v) {
    float r; asm("tanh.approx.f32 %0, %1;" : "=f"(r) : "f"(v)); return r;
}
// pack {lo, hi} floats into bf16x2 (lo -> low 16 bits = lower column)
__device__ __forceinline__ uint32_t packlh(float lo, float hi) {
    uint32_t r;
    asm("cvt.rn.satfinite.bf16x2.f32 %0, %1, %2;" : "=r"(r) : "f"(hi), "f"(lo));
    return r;
}
__device__ __forceinline__ void mma16816(float* d, const uint32_t* a,
                                         uint32_t b0, uint32_t b1) {
    asm volatile(
        "mma.sync.aligned.m16n8k16.row.col.f32.bf16.bf16.f32 "
        "{%0,%1,%2,%3}, {%4,%5,%6,%7}, {%8,%9}, {%0,%1,%2,%3};"
        : "+f"(d[0]), "+f"(d[1]), "+f"(d[2]), "+f"(d[3])
        : "r"(a[0]), "r"(a[1]), "r"(a[2]), "r"(a[3]), "r"(b0), "r"(b1));
}
__device__ __forceinline__ void ldsm4(uint32_t* r, uint32_t addr) {
    asm volatile("ldmatrix.sync.aligned.m8n8.x4.shared.b16 {%0,%1,%2,%3}, [%4];"
                 : "=r"(r[0]), "=r"(r[1]), "=r"(r[2]), "=r"(r[3]) : "r"(addr));
}
__device__ __forceinline__ void sts32(uint32_t addr, uint32_t v) {
    asm volatile("st.shared.b32 [%0], %1;" :: "r"(addr), "r"(v) : "memory");
}
__device__ __forceinline__ void sts128(uint32_t addr, uint32_t a, uint32_t b,
                                       uint32_t c, uint32_t d) {
    asm volatile("st.shared.v4.b32 [%0], {%1,%2,%3,%4};"
                 :: "r"(addr), "r"(a), "r"(b), "r"(c), "r"(d) : "memory");
}

// One GEMM iteration over the extended K (9 k-tiles), TWO 16-row sub-bands.
// FIRST: z=0, only the c columns contribute.  LAST: fuse y = z.h.
// A80/A81 = constant x/ones fragments (hoisted, per band).
template<bool FIRST, bool LAST>
__device__ __forceinline__ void gemm_iter(
    uint32_t bb, uint32_t ccb,
    uint32_t za0, uint32_t za1, uint32_t zs0, uint32_t zs1,
    const float2* h2, const uint32_t A80[4], const uint32_t A81[4],
    float* y, int qc)
{
    uint32_t A0[8][4], A1[8][4];
    if (!FIRST) {
        #pragma unroll
        for (int kt = 0; kt < 8; ++kt) ldsm4(A0[kt], za0 + kt * 32);
        #pragma unroll
        for (int kt = 0; kt < 8; ++kt) ldsm4(A1[kt], za1 + kt * 32);
    }

    #pragma unroll
    for (int ntp = 0; ntp < 8; ++ntp) {
        const uint32_t b0a = bb + (uint32_t)(2 * ntp)     * (8 * LDW);
        const uint32_t b1a = bb + (uint32_t)(2 * ntp + 1) * (8 * LDW);
        float a00[4] = {0.f,0.f,0.f,0.f};   // band0, even n-tile
        float a01[4] = {0.f,0.f,0.f,0.f};   // band0, odd  n-tile
        float a10[4] = {0.f,0.f,0.f,0.f};   // band1, even n-tile
        float a11[4] = {0.f,0.f,0.f,0.f};   // band1, odd  n-tile
        {   // c contribution: merged ldsm4 (b0 lo, b0 hi, b1 lo, b1 hi)
            uint32_t c[4];
            ldsm4(c, ccb + (uint32_t)ntp * (16 * LDW));
            mma16816(a00, A80, c[0], c[1]);
            mma16816(a01, A80, c[2], c[3]);
            mma16816(a10, A81, c[0], c[1]);
            mma16816(a11, A81, c[2], c[3]);
        }
        if (!FIRST) {
            #pragma unroll
            for (int l = 0; l < 4; ++l) {
                uint32_t b0[4], b1[4];
                ldsm4(b0, b0a + l * 64);
                ldsm4(b1, b1a + l * 64);
                mma16816(a00, A0[2 * l],     b0[0], b0[1]);
                mma16816(a10, A1[2 * l],     b0[0], b0[1]);
                mma16816(a01, A0[2 * l],     b1[0], b1[1]);
                mma16816(a11, A1[2 * l],     b1[0], b1[1]);
                mma16816(a00, A0[2 * l + 1], b0[2], b0[3]);
                mma16816(a10, A1[2 * l + 1], b0[2], b0[3]);
                mma16816(a01, A0[2 * l + 1], b1[2], b1[3]);
                mma16816(a11, A1[2 * l + 1], b1[2], b1[3]);
            }
        }
        #pragma unroll
        for (int h = 0; h < 2; ++h) {
            const int nt = 2 * ntp + h;
            const float* ac0 = h ? a01 : a00;
            const float* ac1 = h ? a11 : a10;
            if (LAST) {
                float2 hv = h2[4 * nt + qc];
                y[0] += hv.x * tanh_exact(ac0[0]) + hv.y * tanh_exact(ac0[1]);
                y[1] += hv.x * tanh_exact(ac0[2]) + hv.y * tanh_exact(ac0[3]);
                y[2] += hv.x * tanh_exact(ac1[0]) + hv.y * tanh_exact(ac1[1]);
                y[3] += hv.x * tanh_exact(ac1[2]) + hv.y * tanh_exact(ac1[3]);
            } else {
                uint32_t off = (uint32_t)(nt * 8 + 2 * qc) * 2;
                sts32(zs0 + off,           packlh(tanh_apx(ac0[0]), tanh_apx(ac0[1])));
                sts32(zs0 + 8 * LDW + off, packlh(tanh_apx(ac0[2]), tanh_apx(ac0[3])));
                sts32(zs1 + off,           packlh(tanh_apx(ac1[0]), tanh_apx(ac1[1])));
                sts32(zs1 + 8 * LDW + off, packlh(tanh_apx(ac1[2]), tanh_apx(ac1[3])));
            }
        }
    }
}

__global__ void __launch_bounds__(THREADS, 1)
deq_mma_kernel(const float* __restrict__ x,
               const float* __restrict__ Aw,
               const float* __restrict__ Ab,
               const float* __restrict__ Bw,
               const float* __restrict__ Bb,
               const float* __restrict__ hw,
               const float* __restrict__ hb,
               float* __restrict__ out,
               int nbands)   // 32-row bands
{
    extern __shared__ char smem[];
    const int tid = threadIdx.x;

    // this CTA's static band range (covers all bands, disjoint, ~balanced)
    const unsigned int cta_lo = (unsigned int)(((long long)blockIdx.x * nbands) / gridDim.x);
    const unsigned int cta_hi = (unsigned int)(((long long)(blockIdx.x + 1) * nbands) / gridDim.x);
    unsigned int* cnt = (unsigned int*)(smem + SM_CNT);
    if (tid == 0) *cnt = cta_lo;

    // ---- one-time staging: W~ (bf16, padded rows) and h ----
    for (int idx = tid; idx < 128 * 144; idx += THREADS) {
        int n = idx / 144, k = idx % 144;
        float v;
        if (k < 128) {
            v = Bw[n * 128 + k];
        } else if (k < 132) {            // Aw_hi (bf16 store rounds)
            v = Aw[n * 4 + (k - 128)];
        } else if (k < 136) {            // Aw_lo
            float a = Aw[n * 4 + (k - 132)];
            v = a - __bfloat162float(__float2bfloat16(a));
        } else if (k < 140) {            // Aw_hi again (pairs with x_lo)
            v = Aw[n * 4 + (k - 136)];
        } else if (k == 140) {           // bias_hi
            v = Ab[n] + Bb[n];
        } else if (k == 141) {           // bias_lo
            float b = Ab[n] + Bb[n];
            v = b - __bfloat162float(__float2bfloat16(b));
        } else {
            v = 0.0f;
        }
        *(__nv_bfloat16*)(smem + SM_W + n * LDW + k * 2) = __float2bfloat16(v);
    }
    if (tid < 128) ((float*)(smem + SM_H))[tid] = hw[tid];
    __syncthreads();

    // ---- per-thread constants ----
    const int lane = tid & 31, wid = tid >> 5;
    const int qr = lane >> 2, qc = lane & 3;
    const float2* h2  = (const float2*)(smem + SM_H);
    const uint32_t sb = (uint32_t)__cvta_generic_to_shared(smem);
    const uint32_t bb = sb + SM_W + (uint32_t)(lane & 7) * LDW + (uint32_t)(lane >> 3) * 16;
    // merged c-column ldsm4 base: row = (lane&7) + ((lane>>4)&1)*8 (b0 vs b1),
    // k-group = ((lane>>3)&1)*16, at byte offset 256
    const uint32_t ccb = sb + SM_W
                       + ((uint32_t)(lane & 7) + (uint32_t)((lane >> 4) & 1) * 8) * LDW
                       + 256 + (uint32_t)((lane >> 3) & 1) * 16;
    const uint32_t zb  = sb + SM_Z + (uint32_t)wid * ZSLICE;
    const uint32_t za0 = zb + (uint32_t)(lane & 15) * LDW + (uint32_t)(lane >> 4) * 16;
    const uint32_t za1 = za0 + 16 * LDW;
    const uint32_t zs0 = zb + (uint32_t)qr * LDW;
    const uint32_t zs1 = zs0 + 16 * LDW;
    const float hb0 = hb[0];

    const uint32_t zrow = zb + (uint32_t)lane * LDW;   // prologue: lane = row

    for (;;) {
        // ---- grab next 32-row band from the CTA-local queue ----
        unsigned int band = 0u;
        if (lane == 0) band = atomicAdd(cnt, 1u);
        band = __shfl_sync(0xffffffffu, band, 0);
        if (band >= cta_hi) break;
        const int row0 = (int)band * 32;

        // ---- prologue: write x_hi/x_hi/x_lo/ones columns (bytes 256-287) ----
        __syncwarp();   // previous band's ldsm reads of Z are done
        {
            float4 xv = ((const float4*)x)[row0 + lane];
            float hx = __bfloat162float(__float2bfloat16(xv.x));
            float hy = __bfloat162float(__float2bfloat16(xv.y));
            float hz = __bfloat162float(__float2bfloat16(xv.z));
            float hw_ = __bfloat162float(__float2bfloat16(xv.w));
            uint32_t p0 = packlh(xv.x, xv.y);   // rounds to x_hi
            uint32_t p1 = packlh(xv.z, xv.w);
            sts128(zrow + 256, p0, p1, p0, p1);
            sts128(zrow + 272,
                   packlh(xv.x - hx, xv.y - hy),
                   packlh(xv.z - hz, xv.w - hw_),
                   packlh(1.0f, 1.0f), 0u);
        }
        __syncwarp();

        // ---- hoist A8 fragments: x/ones, constant across the 3 iterations ----
        uint32_t A80[4], A81[4];
        ldsm4(A80, za0 + 256);
        ldsm4(A81, za1 + 256);

        // ---- 3 applications: z1 (c only), z2, z3 + y ----
        float y[4] = {0.f, 0.f, 0.f, 0.f};
        gemm_iter<true,  false>(bb, ccb, za0, za1, zs0, zs1, h2, A80, A81, y, qc);
        __syncwarp();
        gemm_iter<false, false>(bb, ccb, za0, za1, zs0, zs1, h2, A80, A81, y, qc);
        __syncwarp();
        gemm_iter<false, true >(bb, ccb, za0, za1, zs0, zs1, h2, A80, A81, y, qc);

        // ---- reduce y across the 4 lanes sharing a row, write out ----
        #pragma unroll
        for (int k = 0; k < 4; ++k) {
            y[k] += __shfl_xor_sync(0xffffffffu, y[k], 1);
            y[k] += __shfl_xor_sync(0xffffffffu, y[k], 2);
        }
        if (qc == 0) {
            out[row0 + qr]      = y[0] + hb0;
            out[row0 + qr + 8]  = y[1] + hb0;
            out[row0 + qr + 16] = y[2] + hb0;
            out[row0 + qr + 24] = y[3] + hb0;
        }
    }
}

extern "C" void kernel_launch(void* const* d_in, const int* in_sizes, int n_in,
                              void* d_out, int out_size) {
    const float* x  = (const float*)d_in[0];
    const float* Aw = (const float*)d_in[1];
    const float* Ab = (const float*)d_in[2];
    const float* Bw = (const float*)d_in[3];
    const float* Bb = (const float*)d_in[4];
    const float* hw = (const float*)d_in[5];
    const float* hb = (const float*)d_in[6];
    float* out = (float*)d_out;

    int batch  = in_sizes[0] / 4;   // x is [batch, 4]
    int nbands = batch / 32;        // 4096 (32-row bands)
    int grid   = 148;               // persistent: one CTA per SM

    cudaFuncSetAttribute(deq_mma_kernel,
                         cudaFuncAttributeMaxDynamicSharedMemorySize,
                         SM_TOTAL);
    deq_mma_kernel<<<grid, THREADS, SM_TOTAL>>>(x, Aw, Ab, Bw, Bb, hw, hb, out, nbands);
}